// round 8
// baseline (speedup 1.0000x reference)
#include <cuda_runtime.h>
#include <cstdint>
#include <cstddef>

#define N_SIMP 8192
#define KF 8
#define BATCH 64
#define FEAT 128

// ---- kernel 1 tiling: wL = W @ L ----
#define SEG1 16                    // row segments (partial slices)
#define ROWS1 (N_SIMP / SEG1)      // 512 rows per segment
#define COLB1 16                   // column blocks
#define COLS1 (N_SIMP / COLB1)     // 512 cols per block = 128 thr * 4

// ---- kernel 2 tiling: out = wL @ x[b] ----
#define SEG2 8                     // n segments
#define ROWS2 (N_SIMP / SEG2)      // 1024 n per segment

typedef unsigned long long ull;

// Scratch (device globals: allocation-free rule)
__device__ float g_wL_part[SEG1][KF][N_SIMP];          // 4 MB
__device__ float g_wL[KF][N_SIMP];                     // 256 KB
__device__ float g_acc_part[SEG2][KF][BATCH][FEAT];    // 2 MB
__device__ unsigned g_cnt1[COLB1];                     // zero-init; self-resetting
__device__ unsigned g_cnt2[BATCH];                     // zero-init; self-resetting

__device__ __forceinline__ ull pack_dup(float a) {
    ull r; asm("mov.b64 %0, {%1, %1};" : "=l"(r) : "f"(a)); return r;
}
__device__ __forceinline__ void fma2(ull& d, ull a, ull b) {
    // packed f32x2 FMA: d = a*b + d on both halves (FFMA2 in SASS)
    asm("fma.rn.f32x2 %0, %1, %2, %0;" : "+l"(d) : "l"(a), "l"(b));
}
__device__ __forceinline__ float2 unpack2(ull v) {
    float2 r; asm("mov.b64 {%0, %1}, %2;" : "=f"(r.x), "=f"(r.y) : "l"(v)); return r;
}

// ============================================================
// k1: partial wL + fused last-CTA reduce. Block = (colb, seg).
// Thread owns 4 contiguous L columns, all 8 filters (4 k-pairs).
// Double-buffered 8-row blocks -> sustained MLP ~8.
// Last seg-CTA per colb reduces the 16 partial slices -> g_wL.
// ============================================================
__device__ __forceinline__ void k1_compute8(const float4* lv, int mbase,
                                            ull acc[4][4],
                                            const float2 wtp[4][ROWS1]) {
    #pragma unroll
    for (int r = 0; r < 8; r++) {
        ull ld[4] = { pack_dup(lv[r].x), pack_dup(lv[r].y),
                      pack_dup(lv[r].z), pack_dup(lv[r].w) };
        #pragma unroll
        for (int kp = 0; kp < 4; kp++) {
            ull wp = *reinterpret_cast<const ull*>(&wtp[kp][mbase + r]);  // LDS.64 bcast
            #pragma unroll
            for (int j = 0; j < 4; j++) fma2(acc[kp][j], ld[j], wp);
        }
    }
}

__global__ __launch_bounds__(128, 1) void k1_wl(const float* __restrict__ W,
                                                const float* __restrict__ L) {
    const int tid  = threadIdx.x;
    const int colb = blockIdx.x;
    const int seg  = blockIdx.y;
    const int c0   = colb * COLS1 + tid * 4;
    const int m0   = seg * ROWS1;

    __shared__ float2 wtp[4][ROWS1];   // 16 KB, W segment as k-pairs
    __shared__ unsigned s_last;
    for (int idx = tid; idx < 4 * ROWS1; idx += 128) {
        int kp = idx / ROWS1;
        int m  = idx % ROWS1;
        wtp[kp][m] = make_float2(W[(2 * kp) * N_SIMP + m0 + m],
                                 W[(2 * kp + 1) * N_SIMP + m0 + m]);
    }
    __syncthreads();

    ull acc[4][4];
    #pragma unroll
    for (int kp = 0; kp < 4; kp++)
        #pragma unroll
        for (int j = 0; j < 4; j++) acc[kp][j] = 0ULL;

    const float* Lp = L + (size_t)m0 * N_SIMP + c0;

    float4 bufA[8], bufB[8];
    #pragma unroll
    for (int r = 0; r < 8; r++)
        bufA[r] = __ldcs(reinterpret_cast<const float4*>(Lp + (size_t)r * N_SIMP));

    for (int m = 0; m < ROWS1; m += 16) {
        #pragma unroll
        for (int r = 0; r < 8; r++)
            bufB[r] = __ldcs(reinterpret_cast<const float4*>(
                          Lp + (size_t)(m + 8 + r) * N_SIMP));
        k1_compute8(bufA, m, acc, wtp);
        if (m + 16 < ROWS1) {
            #pragma unroll
            for (int r = 0; r < 8; r++)
                bufA[r] = __ldcs(reinterpret_cast<const float4*>(
                              Lp + (size_t)(m + 16 + r) * N_SIMP));
        }
        k1_compute8(bufB, m + 8, acc, wtp);
    }

    #pragma unroll
    for (int kp = 0; kp < 4; kp++) {
        float2 v0 = unpack2(acc[kp][0]);
        float2 v1 = unpack2(acc[kp][1]);
        float2 v2 = unpack2(acc[kp][2]);
        float2 v3 = unpack2(acc[kp][3]);
        float4 lo = make_float4(v0.x, v1.x, v2.x, v3.x);
        float4 hi = make_float4(v0.y, v1.y, v2.y, v3.y);
        __stcs(reinterpret_cast<float4*>(&g_wL_part[seg][2 * kp][c0]),     lo);
        __stcs(reinterpret_cast<float4*>(&g_wL_part[seg][2 * kp + 1][c0]), hi);
    }

    // ---- last-CTA reduce for this column block ----
    __threadfence();
    if (tid == 0) s_last = atomicAdd(&g_cnt1[colb], 1u);
    __syncthreads();
    if (s_last == SEG1 - 1) {
        __threadfence();
        #pragma unroll
        for (int k = 0; k < KF; k++) {
            float4 s = make_float4(0.f, 0.f, 0.f, 0.f);
            #pragma unroll
            for (int sg = 0; sg < SEG1; sg++) {
                float4 v = __ldcs(reinterpret_cast<const float4*>(&g_wL_part[sg][k][c0]));
                s.x += v.x; s.y += v.y; s.z += v.z; s.w += v.w;
            }
            *reinterpret_cast<float4*>(&g_wL[k][c0]) = s;
        }
        if (tid == 0) g_cnt1[colb] = 0u;   // reset for next graph replay
    }
}

// ============================================================
// k2: partial out + fused last-CTA tanh-reduce. Block = (b, seg).
// 128 threads = 32 f-groups (float4 over FEAT) x 4 n-subgroups.
// Double-buffered 8-row blocks (stride 32 rows) -> sustained MLP ~8.
// Epilogue: smem tree-reduce over n-subgroups; last seg-CTA per b
// reduces the 8 partials + tanh -> out.
// ============================================================
__device__ __forceinline__ void k2_compute8(const float4* xv, int nb, int ng,
                                            ull acc[4][4],
                                            const float2 wlp[4][ROWS2]) {
    #pragma unroll
    for (int r = 0; r < 8; r++) {
        int n = nb + ng + 4 * r;
        ull xd[4] = { pack_dup(xv[r].x), pack_dup(xv[r].y),
                      pack_dup(xv[r].z), pack_dup(xv[r].w) };
        #pragma unroll
        for (int kp = 0; kp < 4; kp++) {
            ull wp = *reinterpret_cast<const ull*>(&wlp[kp][n]);   // LDS.64 bcast
            #pragma unroll
            for (int j = 0; j < 4; j++) fma2(acc[kp][j], xd[j], wp);
        }
    }
}

__global__ __launch_bounds__(128, 1) void k2_out(const float* __restrict__ x,
                                                 float* __restrict__ out) {
    const int tid = threadIdx.x;
    const int fg  = tid & 31;
    const int ng  = tid >> 5;
    const int b   = blockIdx.x;
    const int seg = blockIdx.y;
    const int n0  = seg * ROWS2;

    __shared__ float2 wlp[4][ROWS2];   // 32 KB, k-pairs of wL for this segment
    __shared__ unsigned s_last;
    for (int idx = tid; idx < 4 * ROWS2; idx += 128) {
        int kp = idx >> 10;
        int n  = idx & (ROWS2 - 1);
        wlp[kp][n] = make_float2(g_wL[2 * kp][n0 + n], g_wL[2 * kp + 1][n0 + n]);
    }
    __syncthreads();

    ull acc[4][4];
    #pragma unroll
    for (int kp = 0; kp < 4; kp++)
        #pragma unroll
        for (int j = 0; j < 4; j++) acc[kp][j] = 0ULL;

    const float* xb = x + ((size_t)b * N_SIMP + n0) * FEAT + fg * 4;

    float4 bufA[8], bufB[8];
    #pragma unroll
    for (int r = 0; r < 8; r++)
        bufA[r] = __ldcs(reinterpret_cast<const float4*>(
                      xb + (size_t)(ng + 4 * r) * FEAT));

    for (int nb = 0; nb < ROWS2; nb += 64) {
        #pragma unroll
        for (int r = 0; r < 8; r++)
            bufB[r] = __ldcs(reinterpret_cast<const float4*>(
                          xb + (size_t)(nb + 32 + ng + 4 * r) * FEAT));
        k2_compute8(bufA, nb, ng, acc, wlp);
        if (nb + 64 < ROWS2) {
            #pragma unroll
            for (int r = 0; r < 8; r++)
                bufA[r] = __ldcs(reinterpret_cast<const float4*>(
                              xb + (size_t)(nb + 64 + ng + 4 * r) * FEAT));
        }
        k2_compute8(bufB, nb + 32, ng, acc, wlp);
    }

    // ---- epilogue: reduce over the 4 n-subgroups via smem (2 rounds) ----
    __syncthreads();
    float (*rbuf)[32][32] = reinterpret_cast<float (*)[32][32]>(&wlp[0][0]);

    float mine[32];
    #pragma unroll
    for (int kp = 0; kp < 4; kp++) {
        #pragma unroll
        for (int j = 0; j < 4; j++) {
            float2 v = unpack2(acc[kp][j]);
            mine[(2 * kp) * 4 + j]     = v.x;
            mine[(2 * kp + 1) * 4 + j] = v.y;
        }
    }

    if (ng >= 2) {
        #pragma unroll
        for (int t = 0; t < 32; t++) rbuf[ng - 2][fg][t] = mine[t];
    }
    __syncthreads();
    if (ng < 2) {
        #pragma unroll
        for (int t = 0; t < 32; t++) mine[t] += rbuf[ng][fg][t];
    }
    __syncthreads();
    if (ng == 1) {
        #pragma unroll
        for (int t = 0; t < 32; t++) rbuf[0][fg][t] = mine[t];
    }
    __syncthreads();
    if (ng == 0) {
        #pragma unroll
        for (int k = 0; k < 8; k++) {
            float4 o = make_float4(mine[k * 4 + 0] + rbuf[0][fg][k * 4 + 0],
                                   mine[k * 4 + 1] + rbuf[0][fg][k * 4 + 1],
                                   mine[k * 4 + 2] + rbuf[0][fg][k * 4 + 2],
                                   mine[k * 4 + 3] + rbuf[0][fg][k * 4 + 3]);
            __stcs(reinterpret_cast<float4*>(&g_acc_part[seg][k][b][fg * 4]), o);
        }
    }

    // ---- last-CTA final reduce + tanh for this batch ----
    __threadfence();
    if (tid == 0) s_last = atomicAdd(&g_cnt2[b], 1u);
    __syncthreads();
    if (s_last == SEG2 - 1) {
        __threadfence();
        // out[k][b][f]: 8k x 32 f4-groups = 256 float4 outputs; 2 per thread.
        for (int t = tid; t < KF * 32; t += 128) {
            int k  = t >> 5;
            int f4 = t & 31;
            float4 s = make_float4(0.f, 0.f, 0.f, 0.f);
            #pragma unroll
            for (int sg = 0; sg < SEG2; sg++) {
                float4 v = __ldcs(reinterpret_cast<const float4*>(
                               &g_acc_part[sg][k][b][f4 * 4]));
                s.x += v.x; s.y += v.y; s.z += v.z; s.w += v.w;
            }
            float4 o = make_float4(tanhf(s.x), tanhf(s.y), tanhf(s.z), tanhf(s.w));
            *reinterpret_cast<float4*>(
                out + ((size_t)k * BATCH + b) * FEAT + f4 * 4) = o;
        }
        if (tid == 0) g_cnt2[b] = 0u;   // reset for next graph replay
    }
}

// ============================================================
extern "C" void kernel_launch(void* const* d_in, const int* in_sizes, int n_in,
                              void* d_out, int out_size) {
    const float* x = (const float*)d_in[0];   // [B, N, F]
    const float* L = (const float*)d_in[1];   // [N, N]
    const float* W = (const float*)d_in[2];   // [K, N]
    float* out = (float*)d_out;               // [K, B, F]

    k1_wl<<<dim3(COLB1, SEG1), 128>>>(W, L);
    k2_out<<<dim3(BATCH, SEG2), 128>>>(x, out);
}